// round 7
// baseline (speedup 1.0000x reference)
#include <cuda_runtime.h>
#include <cuda_fp16.h>
#include <cstdint>

// Problem constants
#define BB   8192
#define DIN  2048
#define HH   2048
#define K1   4096   // IN + H
#define K2   2048   // IN

// ---------------------------------------------------------------------------
// Scratch (module-load allocated, allowed)
// ---------------------------------------------------------------------------
__device__ __align__(128) __half g_concat_f16[(size_t)BB * K1];  // [B, IN+H] fp16
__device__ __align__(128) __half g_gw_f16[(size_t)HH * K1];      // [H, IN+H] fp16
__device__ __align__(128) __half g_wi_f16[(size_t)HH * K2];      // [H, IN]   fp16

// Output layout (floats): new_h | concat | pre_gate | gate | values | pre_h
#define OFF_NEWH    ((size_t)0)
#define OFF_CONCAT  ((size_t)BB * HH)
#define OFF_PREGATE (OFF_CONCAT + (size_t)BB * K1)
#define OFF_GATE    (OFF_PREGATE + (size_t)BB * HH)
#define OFF_VALUES  (OFF_GATE + (size_t)BB * HH)
#define OFF_PREH    (OFF_VALUES + (size_t)BB * HH)

// ---------------------------------------------------------------------------
// Helpers
// ---------------------------------------------------------------------------
__device__ __forceinline__ uint2 pack4_f16(float4 v) {
    __half2 lo = __floats2half2_rn(v.x, v.y);
    __half2 hi = __floats2half2_rn(v.z, v.w);
    uint2 u;
    u.x = *reinterpret_cast<unsigned*>(&lo);
    u.y = *reinterpret_cast<unsigned*>(&hi);
    return u;
}

__device__ __forceinline__ void cp_async16(uint32_t saddr, const void* gptr) {
    asm volatile("cp.async.cg.shared.global [%0], [%1], 16;" :: "r"(saddr), "l"(gptr));
}

// ---------------------------------------------------------------------------
// Kernel 1: convert inputs to fp16 + emit concat_input output region
// ---------------------------------------------------------------------------
#define N0 ((size_t)BB * DIN / 4)   // input  float4s
#define N1 ((size_t)BB * HH  / 4)   // state  float4s
#define N2 ((size_t)HH * K1  / 4)   // gate_w float4s
#define N3 ((size_t)HH * K2  / 4)   // w_i    float4s
#define NTOT (N0 + N1 + N2 + N3)

__global__ void __launch_bounds__(256) convert_kernel(
    const float4* __restrict__ inp,
    const float4* __restrict__ st,
    const float4* __restrict__ gw,
    const float4* __restrict__ wi,
    float4* __restrict__ out_concat)   // d_out + OFF_CONCAT
{
    size_t idx = (size_t)blockIdx.x * blockDim.x + threadIdx.x;
    if (idx >= NTOT) return;

    uint2* cf  = reinterpret_cast<uint2*>(g_concat_f16);
    uint2* gwf = reinterpret_cast<uint2*>(g_gw_f16);
    uint2* wif = reinterpret_cast<uint2*>(g_wi_f16);

    if (idx < N0) {
        float4 v = inp[idx];
        size_t row = idx >> 9;          // 512 float4 per row
        size_t c   = idx & 511;
        out_concat[row * 1024 + c] = v;           // concat stride = 1024 f4
        cf[row * 1024 + c] = pack4_f16(v);
    } else if (idx < N0 + N1) {
        size_t i = idx - N0;
        float4 v = st[i];
        size_t row = i >> 9;
        size_t c   = i & 511;
        out_concat[row * 1024 + 512 + c] = v;
        cf[row * 1024 + 512 + c] = pack4_f16(v);
    } else if (idx < N0 + N1 + N2) {
        size_t i = idx - N0 - N1;
        gwf[i] = pack4_f16(gw[i]);
    } else {
        size_t i = idx - N0 - N1 - N2;
        wif[i] = pack4_f16(wi[i]);
    }
}

// ---------------------------------------------------------------------------
// Fused dual-GEMM:
//   acc1[B,H] = concat_f16[B,4096] @ gw_f16[H,4096]^T      (128 k-steps)
//   acc2[B,H] = concat_f16[B,0:2048] @ wi_f16[H,2048]^T    (first 64 k-steps,
//                                                            SAME A tiles)
// Epilogue: pre_gate = acc1 + bias; gate = clip(pre_gate,0,1);
//           values = tanh(acc2); pre_h = state*(1-gate)+values*gate; new_h=relu
// Tile 128x128, 512 threads (warp grid 4x4, warp tile 32x32), 3-stage cp.async.
// ---------------------------------------------------------------------------
#define KT_ALL  128   // K1/32
#define KT_DUAL 64    // K2/32
#define ROWPITCH 40   // halves per smem row (80 B)
#define OPBYTES  (128 * ROWPITCH * 2)      // 10240 B per operand per stage
#define STAGES   3
#define SMEM_TOTAL (STAGES * 3 * OPBYTES)  // 92160 B

__global__ void __launch_bounds__(512, 1) fused_gemm_kernel(
    const float* __restrict__ bias,
    const float* __restrict__ state,
    float* __restrict__ out_pregate,
    float* __restrict__ out_gate,
    float* __restrict__ out_values,
    float* __restrict__ out_preh,
    float* __restrict__ out_newh)
{
    extern __shared__ __align__(16) __half sm[];
    // layout: stage s, operand o (0=A,1=B(gw),2=C(wi)) at sm + (s*3+o)*5120 halves
    const uint32_t sbase = (uint32_t)__cvta_generic_to_shared(sm);

    const __half* __restrict__ A = g_concat_f16;
    const __half* __restrict__ G = g_gw_f16;
    const __half* __restrict__ W = g_wi_f16;

    const int tid  = threadIdx.x;
    const int bm   = blockIdx.y;
    const int bn   = blockIdx.x;
    const int warp = tid >> 5;
    const int lane = tid & 31;
    const int wm   = warp & 3;   // rows wm*32
    const int wn   = warp >> 2;  // cols wn*32

    float acc1[2][4][4], acc2[2][4][4];
    #pragma unroll
    for (int i = 0; i < 2; i++)
        #pragma unroll
        for (int j = 0; j < 4; j++)
            #pragma unroll
            for (int k = 0; k < 4; k++) { acc1[i][j][k] = 0.f; acc2[i][j][k] = 0.f; }

    // per-thread load coords: 512 chunks of 16B per operand
    const int lrow = tid >> 2;          // 0..127
    const int lcol = (tid & 3) * 8;     // 0,8,16,24
    const uint32_t sm_off = (uint32_t)(lrow * ROWPITCH + lcol) * 2;

    auto load_tile = [&](int s, int kt) {
        const int k0 = kt * 32;
        const uint32_t st_base = sbase + (uint32_t)(s * 3) * OPBYTES;
        cp_async16(st_base + sm_off,
                   A + (size_t)(bm * 128 + lrow) * K1 + k0 + lcol);
        cp_async16(st_base + OPBYTES + sm_off,
                   G + (size_t)(bn * 128 + lrow) * K1 + k0 + lcol);
        if (kt < KT_DUAL)
            cp_async16(st_base + 2 * OPBYTES + sm_off,
                       W + (size_t)(bn * 128 + lrow) * K2 + k0 + lcol);
        asm volatile("cp.async.commit_group;");
    };

    load_tile(0, 0);
    load_tile(1, 1);

    const int lr = lane & 15;
    const int lchi = (lane >> 4) * 8;

    #pragma unroll 1
    for (int kt = 0; kt < KT_ALL; kt++) {
        const int s = kt % STAGES;
        if (kt + 2 < KT_ALL) asm volatile("cp.async.wait_group 1;" ::: "memory");
        else                 asm volatile("cp.async.wait_group 0;" ::: "memory");
        __syncthreads();
        if (kt + 2 < KT_ALL) load_tile((kt + 2) % STAGES, kt + 2);

        const uint32_t saddrA = sbase + (uint32_t)(s * 3) * OPBYTES;
        const uint32_t saddrB = saddrA + OPBYTES;
        const uint32_t saddrC = saddrA + 2 * OPBYTES;

        #pragma unroll
        for (int kk = 0; kk < 2; kk++) {
            const int lc = lchi + kk * 16;
            uint32_t aa[2][4];
            #pragma unroll
            for (int mt = 0; mt < 2; mt++) {
                uint32_t ad = saddrA + (uint32_t)((wm * 32 + mt * 16 + lr) * ROWPITCH + lc) * 2;
                asm volatile("ldmatrix.sync.aligned.m8n8.x4.shared.b16 {%0,%1,%2,%3}, [%4];"
                             : "=r"(aa[mt][0]), "=r"(aa[mt][1]), "=r"(aa[mt][2]), "=r"(aa[mt][3])
                             : "r"(ad));
            }
            {
                uint32_t bb[2][4];
                #pragma unroll
                for (int l = 0; l < 2; l++) {
                    uint32_t ad = saddrB + (uint32_t)((wn * 32 + l * 16 + lr) * ROWPITCH + lc) * 2;
                    asm volatile("ldmatrix.sync.aligned.m8n8.x4.shared.b16 {%0,%1,%2,%3}, [%4];"
                                 : "=r"(bb[l][0]), "=r"(bb[l][1]), "=r"(bb[l][2]), "=r"(bb[l][3])
                                 : "r"(ad));
                }
                #pragma unroll
                for (int mt = 0; mt < 2; mt++) {
                    #pragma unroll
                    for (int n = 0; n < 4; n++) {
                        uint32_t b0 = bb[n >> 1][n & 1];
                        uint32_t b1 = bb[n >> 1][(n & 1) + 2];
                        asm volatile(
                            "mma.sync.aligned.m16n8k16.row.col.f32.f16.f16.f32 "
                            "{%0,%1,%2,%3}, {%4,%5,%6,%7}, {%8,%9}, {%0,%1,%2,%3};"
                            : "+f"(acc1[mt][n][0]), "+f"(acc1[mt][n][1]),
                              "+f"(acc1[mt][n][2]), "+f"(acc1[mt][n][3])
                            : "r"(aa[mt][0]), "r"(aa[mt][1]), "r"(aa[mt][2]), "r"(aa[mt][3]),
                              "r"(b0), "r"(b1));
                    }
                }
            }
            if (kt < KT_DUAL) {
                uint32_t cc[2][4];
                #pragma unroll
                for (int l = 0; l < 2; l++) {
                    uint32_t ad = saddrC + (uint32_t)((wn * 32 + l * 16 + lr) * ROWPITCH + lc) * 2;
                    asm volatile("ldmatrix.sync.aligned.m8n8.x4.shared.b16 {%0,%1,%2,%3}, [%4];"
                                 : "=r"(cc[l][0]), "=r"(cc[l][1]), "=r"(cc[l][2]), "=r"(cc[l][3])
                                 : "r"(ad));
                }
                #pragma unroll
                for (int mt = 0; mt < 2; mt++) {
                    #pragma unroll
                    for (int n = 0; n < 4; n++) {
                        uint32_t b0 = cc[n >> 1][n & 1];
                        uint32_t b1 = cc[n >> 1][(n & 1) + 2];
                        asm volatile(
                            "mma.sync.aligned.m16n8k16.row.col.f32.f16.f16.f32 "
                            "{%0,%1,%2,%3}, {%4,%5,%6,%7}, {%8,%9}, {%0,%1,%2,%3};"
                            : "+f"(acc2[mt][n][0]), "+f"(acc2[mt][n][1]),
                              "+f"(acc2[mt][n][2]), "+f"(acc2[mt][n][3])
                            : "r"(aa[mt][0]), "r"(aa[mt][1]), "r"(aa[mt][2]), "r"(aa[mt][3]),
                              "r"(b0), "r"(b1));
                    }
                }
            }
        }
        __syncthreads();
    }

    // ---- fused epilogue ----
    const int rbase = bm * 128 + wm * 32 + (lane >> 2);
    const int cbase = bn * 128 + wn * 32 + (lane & 3) * 2;

    #pragma unroll
    for (int mt = 0; mt < 2; mt++) {
        #pragma unroll
        for (int n = 0; n < 4; n++) {
            const int col = cbase + n * 8;
            const float2 b2 = *reinterpret_cast<const float2*>(bias + col);
            #pragma unroll
            for (int h = 0; h < 2; h++) {
                const int r = rbase + mt * 16 + h * 8;
                const size_t off = (size_t)r * HH + col;

                const float p0 = acc1[mt][n][h * 2 + 0] + b2.x;
                const float p1 = acc1[mt][n][h * 2 + 1] + b2.y;
                *reinterpret_cast<float2*>(out_pregate + off) = make_float2(p0, p1);
                const float g0 = fminf(fmaxf(p0, 0.f), 1.f);
                const float g1 = fminf(fmaxf(p1, 0.f), 1.f);
                *reinterpret_cast<float2*>(out_gate + off) = make_float2(g0, g1);

                const float v0 = tanhf(acc2[mt][n][h * 2 + 0]);
                const float v1 = tanhf(acc2[mt][n][h * 2 + 1]);
                const float2 sv = *reinterpret_cast<const float2*>(state + off);
                const float ph0 = sv.x * (1.f - g0) + v0 * g0;
                const float ph1 = sv.y * (1.f - g1) + v1 * g1;
                *reinterpret_cast<float2*>(out_values + off) = make_float2(v0, v1);
                *reinterpret_cast<float2*>(out_preh + off)   = make_float2(ph0, ph1);
                *reinterpret_cast<float2*>(out_newh + off)   = make_float2(fmaxf(ph0, 0.f),
                                                                           fmaxf(ph1, 0.f));
            }
        }
    }
}

// ---------------------------------------------------------------------------
// Launch
// ---------------------------------------------------------------------------
extern "C" void kernel_launch(void* const* d_in, const int* in_sizes, int n_in,
                              void* d_out, int out_size)
{
    const float* input = (const float*)d_in[0];   // [B, IN]
    const float* state = (const float*)d_in[1];   // [B, H]
    const float* gw    = (const float*)d_in[2];   // [H, IN+H]
    const float* bias  = (const float*)d_in[3];   // [H]
    const float* wi    = (const float*)d_in[4];   // [H, IN]
    float* out = (float*)d_out;

    // 1) convert + concat copy
    {
        const int threads = 256;
        const int blocks = (int)((NTOT + threads - 1) / threads);
        convert_kernel<<<blocks, threads>>>(
            (const float4*)input, (const float4*)state,
            (const float4*)gw, (const float4*)wi,
            (float4*)(out + OFF_CONCAT));
    }

    // 2) fused dual-GEMM: all 5 remaining outputs
    {
        static bool attr_set = false;
        if (!attr_set) {
            cudaFuncSetAttribute(fused_gemm_kernel,
                                 cudaFuncAttributeMaxDynamicSharedMemorySize,
                                 SMEM_TOTAL);
            attr_set = true;
        }
        dim3 grid(HH / 128, BB / 128);   // (16, 64)
        fused_gemm_kernel<<<grid, 512, SMEM_TOTAL>>>(
            bias, state,
            out + OFF_PREGATE, out + OFF_GATE,
            out + OFF_VALUES, out + OFF_PREH, out + OFF_NEWH);
    }
}